// round 1
// baseline (speedup 1.0000x reference)
#include <cuda_runtime.h>
#include <cuda_bf16.h>
#include <math.h>

// Hawkes log-likelihood: chunked parallel scan over the linear recurrence
//   H[n,m,k] = exp(-gamma_k * (t_n - t_{n-1})) * (H[n-1,m,k] + [m_{n-1}==m])
//   lam_n    = mu_n + sum_{m,k} alpha[k, m_n, m] * gamma_k * H[n,m,k]
//   out      = sum_n log(lam_n)
//
// Shapes: N=200000, M=50, K=4 (M,K hardcoded; N from in_sizes).
//
// State layout across a warp: entry idx = lane + 32*j (j<7), padded to 224.
//   k = idx & 3  == lane & 3   (fixed per lane -> one exp per lane per event)
//   m = idx >> 2 == (lane>>2) + 8*j

#define MM    50
#define KK    4
#define NP    224          // padded state entries (200 used)
#define AROW  224          // alphaG row stride (per m_n)
#define CNUM  2048         // number of chunks
#define BROW  232          // g_B row: 224 B entries + 4 A entries + pad

__device__ float  g_alphaG[MM * AROW];      // [m'][m*4+k] = alpha[k,m',m]*gamma[k]
__device__ float  g_B[CNUM * BROW];         // per-chunk transfer (B vector + A per k)
__device__ float  g_carry[CNUM * NP];       // carry-in state per chunk
__device__ double g_partial[CNUM];          // per-chunk log-sum partials
__device__ int    g_shift;                  // 0: mi is int32, 1: mi is int64

// ---------------------------------------------------------------------------
// Prep: fold gamma into alpha, transpose to [m'][m*4+k]; detect mi dtype.
// ---------------------------------------------------------------------------
__global__ void k_prep(const float* __restrict__ alpha,
                       const float* __restrict__ gamma,
                       const int*   __restrict__ mi32)
{
    int i = blockIdx.x * blockDim.x + threadIdx.x;
    if (i == 0) {
        // If mi is int64 (little-endian, values < 50), every odd int32 word is 0.
        // If mi is int32, odd words are random marks; P(64 odd words all 0) ~ 0.
        int nz = 0;
        #pragma unroll 1
        for (int q = 0; q < 64; q++) nz |= mi32[2 * q + 1];
        g_shift = (nz == 0) ? 1 : 0;
    }
    if (i >= MM * AROW) return;
    int mp = i / AROW;
    int r  = i % AROW;
    float v = 0.f;
    if (r < MM * KK) {
        int m = r >> 2, k = r & 3;
        v = alpha[k * (MM * MM) + mp * MM + m] * gamma[k];
    }
    g_alphaG[i] = v;
}

// ---------------------------------------------------------------------------
// Phase 1: per-chunk transfer operator (A per k, B per (m,k)), warp per chunk.
// ---------------------------------------------------------------------------
__global__ void k_phase1(const float* __restrict__ ti,
                         const int*   __restrict__ mi32,
                         const float* __restrict__ gamma,
                         int N, int CS)
{
    int w    = (blockIdx.x * blockDim.x + threadIdx.x) >> 5;
    int lane = threadIdx.x & 31;
    if (w >= CNUM) return;
    float* Brow = &g_B[w * BROW];

    long s = (long)w * CS;
    int  e = (int)min((long)N, s + CS);
    if (s >= N) {                      // empty chunk -> identity transfer
        #pragma unroll
        for (int j = 0; j < 7; j++) Brow[lane + 32 * j] = 0.f;
        if (lane < 4) Brow[NP + lane] = 1.f;
        return;
    }

    const int shift = g_shift;
    const float gk  = gamma[lane & 3];
    const int mbase = lane >> 2;

    float S[7];
    #pragma unroll
    for (int j = 0; j < 7; j++) S[j] = 0.f;

    float tprev = (s > 0) ? ti[s - 1] : ti[0];
    int   mprev = (s > 0) ? mi32[(s - 1) << shift] : -1;
    const float t0 = tprev;

    for (int n = (int)s; n < e; n++) {
        float tn = ti[n];
        float a  = __expf(-gk * (tn - tprev));
        #pragma unroll
        for (int j = 0; j < 7; j++)
            S[j] = fmaf(a, S[j], (mprev == mbase + 8 * j) ? a : 0.f);
        tprev = tn;
        mprev = mi32[n << shift];
    }

    #pragma unroll
    for (int j = 0; j < 7; j++) Brow[lane + 32 * j] = S[j];
    if (lane < 4) Brow[NP + lane] = __expf(-gamma[lane] * (tprev - t0));
}

// ---------------------------------------------------------------------------
// Phase 2: sequential scan across chunk transfers. One (m,k) entry per thread.
// ---------------------------------------------------------------------------
__global__ void k_phase2()
{
    int tid = threadIdx.x;          // 224 threads
    int k   = tid & 3;
    float carry = 0.f;
    #pragma unroll 4
    for (int c = 0; c < CNUM; c++) {
        g_carry[c * NP + tid] = carry;
        float A = g_B[c * BROW + NP + k];
        float B = g_B[c * BROW + tid];
        carry = fmaf(A, carry, B);
    }
}

// ---------------------------------------------------------------------------
// Phase 3: replay with carry, compute sum of log(lam). Warp per chunk.
// ---------------------------------------------------------------------------
__global__ void k_phase3(const float* __restrict__ ti,
                         const int*   __restrict__ mi32,
                         const float* __restrict__ mu,
                         const float* __restrict__ gamma,
                         int N, int CS)
{
    __shared__ float sA[MM * AROW];
    for (int i = threadIdx.x; i < MM * AROW; i += blockDim.x)
        sA[i] = g_alphaG[i];
    __syncthreads();

    int w    = (blockIdx.x * blockDim.x + threadIdx.x) >> 5;
    int lane = threadIdx.x & 31;
    if (w >= CNUM) return;

    long s = (long)w * CS;
    int  e = (int)min((long)N, s + CS);
    if (s >= N) {
        if (lane == 0) g_partial[w] = 0.0;
        return;
    }

    const int shift = g_shift;
    const float gk  = gamma[lane & 3];
    const int mbase = lane >> 2;

    float S[7];
    #pragma unroll
    for (int j = 0; j < 7; j++) S[j] = g_carry[w * NP + lane + 32 * j];

    float tprev = (s > 0) ? ti[s - 1] : ti[0];
    int   mprev = (s > 0) ? mi32[(s - 1) << shift] : -1;
    float facc  = 0.f;

    for (int n = (int)s; n < e; n++) {
        float tn = ti[n];
        int   mn = mi32[n << shift];
        float a  = __expf(-gk * (tn - tprev));
        #pragma unroll
        for (int j = 0; j < 7; j++)
            S[j] = fmaf(a, S[j], (mprev == mbase + 8 * j) ? a : 0.f);

        const float* row = &sA[mn * AROW];
        float dot = 0.f;
        #pragma unroll
        for (int j = 0; j < 7; j++)
            dot = fmaf(row[lane + 32 * j], S[j], dot);

        #pragma unroll
        for (int o = 16; o > 0; o >>= 1)
            dot += __shfl_xor_sync(0xffffffffu, dot, o);

        if (lane == 0) facc += __logf(mu[n] + dot);
        tprev = tn;
        mprev = mn;
    }
    if (lane == 0) g_partial[w] = (double)facc;
}

// ---------------------------------------------------------------------------
// Final: deterministic tree reduce of per-chunk partials (fixed order).
// ---------------------------------------------------------------------------
__global__ void k_final(float* __restrict__ out)
{
    __shared__ double sd[1024];
    int tid = threadIdx.x;
    sd[tid] = g_partial[tid] + g_partial[tid + 1024];
    __syncthreads();
    #pragma unroll
    for (int o = 512; o > 0; o >>= 1) {
        if (tid < o) sd[tid] += sd[tid + o];
        __syncthreads();
    }
    if (tid == 0) out[0] = (float)sd[0];
}

// ---------------------------------------------------------------------------
extern "C" void kernel_launch(void* const* d_in, const int* in_sizes, int n_in,
                              void* d_out, int out_size)
{
    const float* ti    = (const float*)d_in[0];
    const int*   mi32  = (const int*)  d_in[1];   // int32 or int64; detected at runtime
    const float* mu    = (const float*)d_in[2];
    const float* alpha = (const float*)d_in[3];
    const float* gamma = (const float*)d_in[4];
    float* out = (float*)d_out;

    int N  = in_sizes[0];
    int CS = (N + CNUM - 1) / CNUM;

    k_prep  <<<(MM * AROW + 255) / 256, 256>>>(alpha, gamma, mi32);
    k_phase1<<<CNUM / 4, 128>>>(ti, mi32, gamma, N, CS);
    k_phase2<<<1, 224>>>();
    k_phase3<<<CNUM / 4, 128>>>(ti, mi32, mu, gamma, N, CS);
    k_final <<<1, 1024>>>(out);
}

// round 3
// speedup vs baseline: 2.1127x; 2.1127x over previous
#include <cuda_runtime.h>
#include <cuda_bf16.h>
#include <math.h>

// Hawkes log-likelihood: chunked parallel scan over the linear recurrence
//   H[n,m,k] = exp(-gamma_k * (t_n - t_{n-1})) * (H[n-1,m,k] + [m_{n-1}==m])
//   lam_n    = mu_n + sum_{m,k} alpha[k, m_n, m] * gamma_k * H[n,m,k]
//   out      = sum_n log(lam_n)
//
// Shapes: N=200000, M=50, K=4 (M,K hardcoded; N from in_sizes).
//
// State layout across a warp: entry idx = lane + 32*j (j<7), padded to 224.
//   k = idx & 3  == lane & 3   (fixed per lane -> one exp per lane per event)
//   m = idx >> 2 == (lane>>2) + 8*j

#define MM    50
#define KK    4
#define NP    224          // padded state entries (200 used)
#define AROW  224          // alphaG row stride (per m_n)
#define CNUM  4096         // number of chunks
#define BROW  232          // g_B row: 224 B entries + 4 A entries + pad (16B-mult)
#define TILE  32           // chunks per smem tile in phase2
#define NT    (CNUM / TILE)

__device__ __align__(16) float  g_alphaG[MM * AROW];  // [m'][m*4+k] = alpha[k,m',m]*gamma[k]
__device__ __align__(16) float  g_B[CNUM * BROW];     // per-chunk transfer (B vector + A per k)
__device__ __align__(16) float  g_carry[CNUM * NP];   // carry-in state per chunk
__device__ double g_partial[CNUM];                    // per-chunk log-sum partials
__device__ int    g_shift;                            // 0: mi is int32, 1: mi is int64

// ---------------------------------------------------------------------------
// Prep: fold gamma into alpha, transpose to [m'][m*4+k]; detect mi dtype.
// ---------------------------------------------------------------------------
__global__ void k_prep(const float* __restrict__ alpha,
                       const float* __restrict__ gamma,
                       const int*   __restrict__ mi32)
{
    int i = blockIdx.x * blockDim.x + threadIdx.x;
    if (i == 0) {
        // If mi is int64 (little-endian, values < 50), every odd int32 word is 0.
        int nz = 0;
        #pragma unroll 1
        for (int q = 0; q < 64; q++) nz |= mi32[2 * q + 1];
        g_shift = (nz == 0) ? 1 : 0;
    }
    if (i >= MM * AROW) return;
    int mp = i / AROW;
    int r  = i % AROW;
    float v = 0.f;
    if (r < MM * KK) {
        int m = r >> 2, k = r & 3;
        v = alpha[k * (MM * MM) + mp * MM + m] * gamma[k];
    }
    g_alphaG[i] = v;
}

// ---------------------------------------------------------------------------
// Phase 1: per-chunk transfer operator (A per k, B per (m,k)), warp per chunk.
// ---------------------------------------------------------------------------
__global__ void k_phase1(const float* __restrict__ ti,
                         const int*   __restrict__ mi32,
                         const float* __restrict__ gamma,
                         int N, int CS)
{
    int w    = (blockIdx.x * blockDim.x + threadIdx.x) >> 5;
    int lane = threadIdx.x & 31;
    if (w >= CNUM) return;
    float* Brow = &g_B[w * BROW];

    long s = (long)w * CS;
    int  e = (int)min((long)N, s + CS);
    if (s >= N) {                      // empty chunk -> identity transfer
        #pragma unroll
        for (int j = 0; j < 7; j++) Brow[lane + 32 * j] = 0.f;
        if (lane < 4) Brow[NP + lane] = 1.f;
        return;
    }

    const int shift = g_shift;
    const float gk  = gamma[lane & 3];
    const int mbase = lane >> 2;

    float S[7];
    #pragma unroll
    for (int j = 0; j < 7; j++) S[j] = 0.f;

    float tprev = (s > 0) ? ti[s - 1] : ti[0];
    int   mprev = (s > 0) ? mi32[(s - 1) << shift] : -1;
    const float t0 = tprev;

    for (int n = (int)s; n < e; n++) {
        float tn = ti[n];
        float a  = __expf(-gk * (tn - tprev));
        #pragma unroll
        for (int j = 0; j < 7; j++)
            S[j] = fmaf(a, S[j], (mprev == mbase + 8 * j) ? a : 0.f);
        tprev = tn;
        mprev = mi32[n << shift];
    }

    #pragma unroll
    for (int j = 0; j < 7; j++) Brow[lane + 32 * j] = S[j];
    if (lane < 4) Brow[NP + lane] = __expf(-gamma[lane] * (tprev - t0));
}

// ---------------------------------------------------------------------------
// Phase 2: sequential scan across chunk transfers, one (m,k) entry per thread.
// Double-buffered smem tiles: coalesced float4 global loads overlap the
// dependent FMA chain (which reads only smem).
// ---------------------------------------------------------------------------
__global__ void k_phase2()
{
    __shared__ __align__(16) float sB[2][TILE * BROW];   // 2 x 29696 B

    int tid = threadIdx.x;          // 224 threads
    int k   = tid & 3;
    float carry = 0.f;

    // preload tile 0
    {
        const float4* src = (const float4*)&g_B[0];
        float4*       dst = (float4*)sB[0];
        for (int i = tid; i < TILE * BROW / 4; i += 224) dst[i] = src[i];
    }
    __syncthreads();

    for (int t = 0; t < NT; t++) {
        int buf = t & 1;
        // prefetch next tile into the other buffer
        if (t + 1 < NT) {
            const float4* src = (const float4*)&g_B[(t + 1) * TILE * BROW];
            float4*       dst = (float4*)sB[buf ^ 1];
            for (int i = tid; i < TILE * BROW / 4; i += 224) dst[i] = src[i];
        }
        // scan this tile (fully unrolled: all LDS issued early, FMA chain only)
        #pragma unroll
        for (int c = 0; c < TILE; c++) {
            int ch = t * TILE + c;
            g_carry[ch * NP + tid] = carry;
            float A = sB[buf][c * BROW + NP + k];
            float B = sB[buf][c * BROW + tid];
            carry = fmaf(A, carry, B);
        }
        __syncthreads();
    }
}

// ---------------------------------------------------------------------------
// Phase 3: replay with carry, compute sum of log(lam). Warp per chunk.
// ---------------------------------------------------------------------------
__global__ void k_phase3(const float* __restrict__ ti,
                         const int*   __restrict__ mi32,
                         const float* __restrict__ mu,
                         const float* __restrict__ gamma,
                         int N, int CS)
{
    __shared__ float sA[MM * AROW];
    for (int i = threadIdx.x; i < MM * AROW; i += blockDim.x)
        sA[i] = g_alphaG[i];
    __syncthreads();

    int w    = (blockIdx.x * blockDim.x + threadIdx.x) >> 5;
    int lane = threadIdx.x & 31;
    if (w >= CNUM) return;

    long s = (long)w * CS;
    int  e = (int)min((long)N, s + CS);
    if (s >= N) {
        if (lane == 0) g_partial[w] = 0.0;
        return;
    }

    const int shift = g_shift;
    const float gk  = gamma[lane & 3];
    const int mbase = lane >> 2;

    float S[7];
    #pragma unroll
    for (int j = 0; j < 7; j++) S[j] = g_carry[w * NP + lane + 32 * j];

    float tprev = (s > 0) ? ti[s - 1] : ti[0];
    int   mprev = (s > 0) ? mi32[(s - 1) << shift] : -1;
    float facc  = 0.f;

    for (int n = (int)s; n < e; n++) {
        float tn = ti[n];
        int   mn = mi32[n << shift];
        float a  = __expf(-gk * (tn - tprev));
        #pragma unroll
        for (int j = 0; j < 7; j++)
            S[j] = fmaf(a, S[j], (mprev == mbase + 8 * j) ? a : 0.f);

        const float* row = &sA[mn * AROW];
        float dot = 0.f;
        #pragma unroll
        for (int j = 0; j < 7; j++)
            dot = fmaf(row[lane + 32 * j], S[j], dot);

        #pragma unroll
        for (int o = 16; o > 0; o >>= 1)
            dot += __shfl_xor_sync(0xffffffffu, dot, o);

        if (lane == 0) facc += __logf(mu[n] + dot);
        tprev = tn;
        mprev = mn;
    }
    if (lane == 0) g_partial[w] = (double)facc;
}

// ---------------------------------------------------------------------------
// Final: deterministic tree reduce of per-chunk partials (fixed order).
// ---------------------------------------------------------------------------
__global__ void k_final(float* __restrict__ out)
{
    __shared__ double sd[1024];
    int tid = threadIdx.x;
    double v = 0.0;
    #pragma unroll
    for (int i = 0; i < CNUM / 1024; i++) v += g_partial[tid + i * 1024];
    sd[tid] = v;
    __syncthreads();
    #pragma unroll
    for (int o = 512; o > 0; o >>= 1) {
        if (tid < o) sd[tid] += sd[tid + o];
        __syncthreads();
    }
    if (tid == 0) out[0] = (float)sd[0];
}

// ---------------------------------------------------------------------------
extern "C" void kernel_launch(void* const* d_in, const int* in_sizes, int n_in,
                              void* d_out, int out_size)
{
    const float* ti    = (const float*)d_in[0];
    const int*   mi32  = (const int*)  d_in[1];   // int32 or int64; detected at runtime
    const float* mu    = (const float*)d_in[2];
    const float* alpha = (const float*)d_in[3];
    const float* gamma = (const float*)d_in[4];
    float* out = (float*)d_out;

    int N  = in_sizes[0];
    int CS = (N + CNUM - 1) / CNUM;

    k_prep  <<<(MM * AROW + 255) / 256, 256>>>(alpha, gamma, mi32);
    k_phase1<<<CNUM / 4, 128>>>(ti, mi32, gamma, N, CS);
    k_phase2<<<1, 224>>>();
    k_phase3<<<CNUM / 4, 128>>>(ti, mi32, mu, gamma, N, CS);
    k_final <<<1, 1024>>>(out);
}

// round 8
// speedup vs baseline: 6.0782x; 2.8770x over previous
#include <cuda_runtime.h>
#include <cuda_bf16.h>
#include <math.h>

// Hawkes log-likelihood: hierarchical chunked scan over the linear recurrence
//   H[n,m,k] = exp(-gamma_k * dt_n) * (H[n-1,m,k] + onehot(m_{n-1}))
//   lam_n    = mu_n + sum_{m,k} alpha[k, m_n, m] * gamma_k * H[n,m,k]
//   out      = sum_n log(lam_n)
//
// State layout across a warp: entry idx = lane + 32*j (j<7), padded to 224.
//   k = idx & 3  == lane & 3   (one exp per lane per event)
//   m = idx >> 2 == (lane>>2) + 8*j

#define MM     50
#define KK     4
#define NP     224          // padded state entries (200 used)
#define AROW   224          // alphaG row stride (>= NP so dot reads stay in-row)
#define CNUM   8192         // chunks
#define GROUP  64           // chunks per scan group
#define NGROUP (CNUM / GROUP)   // 128
#define BROW   232          // transfer row: 224 B + 4 A + pad

__device__ __align__(16) float  g_alphaG[MM * AROW];   // [m'][m*4+k] = alpha[k,m',m]*gamma[k]
__device__ __align__(16) float  g_B[CNUM * BROW];      // per-chunk transfer
__device__ __align__(16) float  g_Apre[CNUM * 4];      // A-prefix within group, per k
__device__ __align__(16) float  g_GB[NGROUP * BROW];   // per-group transfer
__device__ __align__(16) float  g_gc[NGROUP * NP];     // group carry-in
__device__ __align__(16) float  g_carry[CNUM * NP];    // local (in-group) prefix per chunk
__device__ double g_partial[CNUM];
__device__ int    g_shift;                             // 0: mi int32, 1: mi int64

// ---------------------------------------------------------------------------
__global__ void k_prep(const float* __restrict__ alpha,
                       const float* __restrict__ gamma,
                       const int*   __restrict__ mi32)
{
    int i = blockIdx.x * blockDim.x + threadIdx.x;
    if (i == 0) {
        int nz = 0;
        #pragma unroll 1
        for (int q = 0; q < 64; q++) nz |= mi32[2 * q + 1];
        g_shift = (nz == 0) ? 1 : 0;
    }
    if (i >= MM * AROW) return;
    int mp = i / AROW;
    int r  = i % AROW;
    float v = 0.f;
    if (r < MM * KK) {
        int m = r >> 2, k = r & 3;
        v = alpha[k * (MM * MM) + mp * MM + m] * gamma[k];
    }
    g_alphaG[i] = v;
}

// ---------------------------------------------------------------------------
// Phase 1: per-chunk transfer (A per k, B per (m,k)). Warp per chunk.
// ---------------------------------------------------------------------------
__global__ void __launch_bounds__(256) k_phase1(
        const float* __restrict__ ti,
        const int*   __restrict__ mi32,
        const float* __restrict__ gamma,
        int N, int CS)
{
    int w    = (blockIdx.x * blockDim.x + threadIdx.x) >> 5;
    int lane = threadIdx.x & 31;
    if (w >= CNUM) return;
    float* Brow = &g_B[w * BROW];

    long s = (long)w * CS;
    int  e = (int)min((long)N, s + CS);
    if (s >= N) {                       // identity transfer
        #pragma unroll
        for (int j = 0; j < 7; j++) Brow[lane + 32 * j] = 0.f;
        if (lane < 4) Brow[NP + lane] = 1.f;
        return;
    }

    const int shift = g_shift;
    const float gk  = gamma[lane & 3];
    const int mbase = lane >> 2;

    float S[7];
    #pragma unroll
    for (int j = 0; j < 7; j++) S[j] = 0.f;

    float tprev = (s > 0) ? ti[s - 1] : ti[0];
    int   mprev = (s > 0) ? mi32[(s - 1) << shift] : -1;
    const float t0 = tprev;

    for (int n = (int)s; n < e; n++) {
        float tn = ti[n];
        float a  = __expf(-gk * (tn - tprev));
        #pragma unroll
        for (int j = 0; j < 7; j++)
            S[j] = fmaf(a, S[j], (mprev == mbase + 8 * j) ? a : 0.f);
        tprev = tn;
        mprev = mi32[n << shift];
    }

    #pragma unroll
    for (int j = 0; j < 7; j++) Brow[lane + 32 * j] = S[j];
    if (lane < 4) Brow[NP + lane] = __expf(-gamma[lane] * (tprev - t0));
}

// ---------------------------------------------------------------------------
// Phase 2a: per-group scan. Block g scans its 64 chunk transfers, storing the
// in-group prefix carry + A-prefix per chunk, and emits the group transfer.
// ---------------------------------------------------------------------------
__global__ void __launch_bounds__(NP) k_phase2a()
{
    int g   = blockIdx.x;
    int tid = threadIdx.x;          // 224
    int k   = tid & 3;
    int c0  = g * GROUP;

    float carry = 0.f;
    float Aprod = 1.f;

    #pragma unroll 8
    for (int c = 0; c < GROUP; c++) {
        int ch  = c0 + c;
        float A = g_B[ch * BROW + NP + k];
        float B = g_B[ch * BROW + tid];
        g_carry[ch * NP + tid] = carry;
        if (tid < 4) g_Apre[ch * 4 + tid] = Aprod;
        carry = fmaf(A, carry, B);
        Aprod *= A;
    }
    g_GB[g * BROW + tid] = carry;
    if (tid < 4) g_GB[g * BROW + NP + tid] = Aprod;
}

// ---------------------------------------------------------------------------
// Phase 2b: scan the 128 group transfers (single block, short chain).
// ---------------------------------------------------------------------------
__global__ void __launch_bounds__(NP) k_phase2b()
{
    int tid = threadIdx.x;          // 224
    int k   = tid & 3;
    float carry = 0.f;
    #pragma unroll 8
    for (int g = 0; g < NGROUP; g++) {
        g_gc[g * NP + tid] = carry;
        float A = g_GB[g * BROW + NP + k];
        float B = g_GB[g * BROW + tid];
        carry = fmaf(A, carry, B);
    }
}

// ---------------------------------------------------------------------------
// Phase 3: replay with fixed-up carry, accumulate sum of log(lam).
// Warp per chunk; 16 warps/block share the alphaG tile.
// ---------------------------------------------------------------------------
__global__ void __launch_bounds__(512) k_phase3(
        const float* __restrict__ ti,
        const int*   __restrict__ mi32,
        const float* __restrict__ mu,
        const float* __restrict__ gamma,
        int N, int CS)
{
    __shared__ float sA[MM * AROW];
    for (int i = threadIdx.x; i < MM * AROW; i += blockDim.x)
        sA[i] = g_alphaG[i];
    __syncthreads();

    int w    = blockIdx.x * (blockDim.x >> 5) + (threadIdx.x >> 5);
    int lane = threadIdx.x & 31;
    if (w >= CNUM) return;

    long s = (long)w * CS;
    int  e = (int)min((long)N, s + CS);
    if (s >= N) {
        if (lane == 0) g_partial[w] = 0.0;
        return;
    }

    const int shift = g_shift;
    const float gk  = gamma[lane & 3];
    const int mbase = lane >> 2;
    const int grp   = w / GROUP;

    // carry fixup: S = Apre * group_carry + local_prefix
    const float Apre = g_Apre[w * 4 + (lane & 3)];
    float S[7];
    #pragma unroll
    for (int j = 0; j < 7; j++)
        S[j] = fmaf(Apre, g_gc[grp * NP + lane + 32 * j],
                    g_carry[w * NP + lane + 32 * j]);

    float tprev = (s > 0) ? ti[s - 1] : ti[0];
    int   mprev = (s > 0) ? mi32[(s - 1) << shift] : -1;
    float facc  = 0.f;

    for (int n = (int)s; n < e; n++) {
        float tn = ti[n];
        int   mn = mi32[n << shift];
        float a  = __expf(-gk * (tn - tprev));
        #pragma unroll
        for (int j = 0; j < 7; j++)
            S[j] = fmaf(a, S[j], (mprev == mbase + 8 * j) ? a : 0.f);

        const float* row = &sA[mn * AROW];
        float dot = 0.f;
        #pragma unroll
        for (int j = 0; j < 7; j++)
            dot = fmaf(row[lane + 32 * j], S[j], dot);

        // warp-wide fp32 sum: 5-step butterfly (redux.sync.f32 not on sm_103)
        #pragma unroll
        for (int o = 16; o > 0; o >>= 1)
            dot += __shfl_xor_sync(0xffffffffu, dot, o);

        if (lane == 0) facc += __logf(mu[n] + dot);
        tprev = tn;
        mprev = mn;
    }
    if (lane == 0) g_partial[w] = (double)facc;
}

// ---------------------------------------------------------------------------
__global__ void k_final(float* __restrict__ out)
{
    __shared__ double sd[1024];
    int tid = threadIdx.x;
    double v = 0.0;
    #pragma unroll
    for (int i = 0; i < CNUM / 1024; i++) v += g_partial[tid + i * 1024];
    sd[tid] = v;
    __syncthreads();
    #pragma unroll
    for (int o = 512; o > 0; o >>= 1) {
        if (tid < o) sd[tid] += sd[tid + o];
        __syncthreads();
    }
    if (tid == 0) out[0] = (float)sd[0];
}

// ---------------------------------------------------------------------------
extern "C" void kernel_launch(void* const* d_in, const int* in_sizes, int n_in,
                              void* d_out, int out_size)
{
    const float* ti    = (const float*)d_in[0];
    const int*   mi32  = (const int*)  d_in[1];   // int32 or int64; runtime-detected
    const float* mu    = (const float*)d_in[2];
    const float* alpha = (const float*)d_in[3];
    const float* gamma = (const float*)d_in[4];
    float* out = (float*)d_out;

    int N  = in_sizes[0];
    int CS = (N + CNUM - 1) / CNUM;

    k_prep   <<<(MM * AROW + 255) / 256, 256>>>(alpha, gamma, mi32);
    k_phase1 <<<CNUM / 8, 256>>>(ti, mi32, gamma, N, CS);
    k_phase2a<<<NGROUP, NP>>>();
    k_phase2b<<<1, NP>>>();
    k_phase3 <<<CNUM / 16, 512>>>(ti, mi32, mu, gamma, N, CS);
    k_final  <<<1, 1024>>>(out);
}

// round 10
// speedup vs baseline: 6.3344x; 1.0421x over previous
#include <cuda_runtime.h>
#include <cuda_bf16.h>
#include <math.h>

// Hawkes log-likelihood: hierarchical chunked scan over the linear recurrence
//   H[n,m,k] = exp(-gamma_k * dt_n) * (H[n-1,m,k] + onehot(m_{n-1}))
//   lam_n    = mu_n + sum_{m,k} alpha[k, m_n, m] * gamma_k * H[n,m,k]
//   out      = sum_n log(lam_n)
//
// State layout across a warp: entry idx = lane + 32*j (j<7), padded to 224.
//   k = idx & 3  == lane & 3   (one exp per lane per event)
//   m = idx >> 2 == (lane>>2) + 8*j

#define MM     50
#define KK     4
#define NP     224          // padded state entries (200 used)
#define AROW   224          // alphaG row stride (>= NP so dot reads stay in-row)
#define CNUM   8192         // chunks
#define GROUP  64           // chunks per scan group
#define NGROUP (CNUM / GROUP)   // 128
#define BROW   232          // transfer row: 224 B + 4 A + pad
#define B2A    16           // phase2a register batch
#define B2B    32           // phase2b register batch

__device__ __align__(16) float  g_alphaG[MM * AROW];   // [m'][m*4+k] = alpha[k,m',m]*gamma[k]
__device__ __align__(16) float  g_B[CNUM * BROW];      // per-chunk transfer
__device__ __align__(16) float  g_Apre[CNUM * 4];      // A-prefix within group, per k
__device__ __align__(16) float  g_GB[NGROUP * BROW];   // per-group transfer
__device__ __align__(16) float  g_gc[NGROUP * NP];     // group carry-in
__device__ __align__(16) float  g_carry[CNUM * NP];    // local (in-group) prefix per chunk
__device__ double g_partial[CNUM];
__device__ int    g_shift;                             // 0: mi int32, 1: mi int64

// ---------------------------------------------------------------------------
__global__ void k_prep(const float* __restrict__ alpha,
                       const float* __restrict__ gamma,
                       const int*   __restrict__ mi32)
{
    int i = blockIdx.x * blockDim.x + threadIdx.x;
    if (i == 0) {
        int nz = 0;
        #pragma unroll 1
        for (int q = 0; q < 64; q++) nz |= mi32[2 * q + 1];
        g_shift = (nz == 0) ? 1 : 0;
    }
    if (i >= MM * AROW) return;
    int mp = i / AROW;
    int r  = i % AROW;
    float v = 0.f;
    if (r < MM * KK) {
        int m = r >> 2, k = r & 3;
        v = alpha[k * (MM * MM) + mp * MM + m] * gamma[k];
    }
    g_alphaG[i] = v;
}

// ---------------------------------------------------------------------------
// Phase 1: per-chunk transfer (A per k, B per (m,k)). Warp per chunk.
// ---------------------------------------------------------------------------
__global__ void __launch_bounds__(256) k_phase1(
        const float* __restrict__ ti,
        const int*   __restrict__ mi32,
        const float* __restrict__ gamma,
        int N, int CS)
{
    int w    = (blockIdx.x * blockDim.x + threadIdx.x) >> 5;
    int lane = threadIdx.x & 31;
    if (w >= CNUM) return;
    float* Brow = &g_B[w * BROW];

    long s = (long)w * CS;
    int  e = (int)min((long)N, s + CS);
    if (s >= N) {                       // identity transfer
        #pragma unroll
        for (int j = 0; j < 7; j++) Brow[lane + 32 * j] = 0.f;
        if (lane < 4) Brow[NP + lane] = 1.f;
        return;
    }

    const int shift = g_shift;
    const float gk  = gamma[lane & 3];
    const int mbase = lane >> 2;

    float S[7];
    #pragma unroll
    for (int j = 0; j < 7; j++) S[j] = 0.f;

    float tprev = (s > 0) ? ti[s - 1] : ti[0];
    int   mprev = (s > 0) ? mi32[(s - 1) << shift] : -1;
    const float t0 = tprev;

    for (int n = (int)s; n < e; n++) {
        float tn = ti[n];
        float a  = __expf(-gk * (tn - tprev));
        #pragma unroll
        for (int j = 0; j < 7; j++)
            S[j] = fmaf(a, S[j], (mprev == mbase + 8 * j) ? a : 0.f);
        tprev = tn;
        mprev = mi32[n << shift];
    }

    #pragma unroll
    for (int j = 0; j < 7; j++) Brow[lane + 32 * j] = S[j];
    if (lane < 4) Brow[NP + lane] = __expf(-gamma[lane] * (tprev - t0));
}

// ---------------------------------------------------------------------------
// Phase 2a: per-group scan. Register-batched loads (address-independent) so
// L2 latency is exposed once per batch, not once per element.
// ---------------------------------------------------------------------------
__global__ void __launch_bounds__(NP) k_phase2a()
{
    int g   = blockIdx.x;
    int tid = threadIdx.x;          // 224
    int k   = tid & 3;
    int c0  = g * GROUP;

    float carry = 0.f;
    float Aprod = 1.f;

    #pragma unroll 1
    for (int t = 0; t < GROUP; t += B2A) {
        float Av[B2A], Bv[B2A];
        #pragma unroll
        for (int i = 0; i < B2A; i++) {
            int ch = c0 + t + i;
            Av[i] = g_B[ch * BROW + NP + k];
            Bv[i] = g_B[ch * BROW + tid];
        }
        #pragma unroll
        for (int i = 0; i < B2A; i++) {
            int ch = c0 + t + i;
            g_carry[ch * NP + tid] = carry;
            if (tid < 4) g_Apre[ch * 4 + tid] = Aprod;
            carry = fmaf(Av[i], carry, Bv[i]);
            Aprod *= Av[i];
        }
    }
    g_GB[g * BROW + tid] = carry;
    if (tid < 4) g_GB[g * BROW + NP + tid] = Aprod;
}

// ---------------------------------------------------------------------------
// Phase 2b: scan the 128 group transfers. Single block; register-batched
// prefetch (32 pairs in flight) collapses the per-iteration latency exposure.
// ---------------------------------------------------------------------------
__global__ void __launch_bounds__(NP) k_phase2b()
{
    int tid = threadIdx.x;          // 224
    int k   = tid & 3;
    float carry = 0.f;

    #pragma unroll 1
    for (int t = 0; t < NGROUP; t += B2B) {
        float Av[B2B], Bv[B2B];
        #pragma unroll
        for (int i = 0; i < B2B; i++) {
            int g = t + i;
            Av[i] = g_GB[g * BROW + NP + k];
            Bv[i] = g_GB[g * BROW + tid];
        }
        #pragma unroll
        for (int i = 0; i < B2B; i++) {
            int g = t + i;
            g_gc[g * NP + tid] = carry;
            carry = fmaf(Av[i], carry, Bv[i]);
        }
    }
}

// ---------------------------------------------------------------------------
// Phase 3: replay with fixed-up carry, accumulate sum of log(lam).
// Warp per chunk; 16 warps/block share the alphaG tile.
// ---------------------------------------------------------------------------
__global__ void __launch_bounds__(512) k_phase3(
        const float* __restrict__ ti,
        const int*   __restrict__ mi32,
        const float* __restrict__ mu,
        const float* __restrict__ gamma,
        int N, int CS)
{
    __shared__ float sA[MM * AROW];
    for (int i = threadIdx.x; i < MM * AROW; i += blockDim.x)
        sA[i] = g_alphaG[i];
    __syncthreads();

    int w    = blockIdx.x * (blockDim.x >> 5) + (threadIdx.x >> 5);
    int lane = threadIdx.x & 31;
    if (w >= CNUM) return;

    long s = (long)w * CS;
    int  e = (int)min((long)N, s + CS);
    if (s >= N) {
        if (lane == 0) g_partial[w] = 0.0;
        return;
    }

    const int shift = g_shift;
    const float gk  = gamma[lane & 3];
    const int mbase = lane >> 2;
    const int grp   = w / GROUP;

    // carry fixup: S = Apre * group_carry + local_prefix
    const float Apre = g_Apre[w * 4 + (lane & 3)];
    float S[7];
    #pragma unroll
    for (int j = 0; j < 7; j++)
        S[j] = fmaf(Apre, g_gc[grp * NP + lane + 32 * j],
                    g_carry[w * NP + lane + 32 * j]);

    float tprev = (s > 0) ? ti[s - 1] : ti[0];
    int   mprev = (s > 0) ? mi32[(s - 1) << shift] : -1;
    float facc  = 0.f;

    for (int n = (int)s; n < e; n++) {
        float tn = ti[n];
        int   mn = mi32[n << shift];
        float a  = __expf(-gk * (tn - tprev));
        #pragma unroll
        for (int j = 0; j < 7; j++)
            S[j] = fmaf(a, S[j], (mprev == mbase + 8 * j) ? a : 0.f);

        const float* row = &sA[mn * AROW];
        float dot = 0.f;
        #pragma unroll
        for (int j = 0; j < 7; j++)
            dot = fmaf(row[lane + 32 * j], S[j], dot);

        // warp-wide fp32 sum: 5-step butterfly (redux.sync.f32 not on sm_103)
        #pragma unroll
        for (int o = 16; o > 0; o >>= 1)
            dot += __shfl_xor_sync(0xffffffffu, dot, o);

        if (lane == 0) facc += __logf(mu[n] + dot);
        tprev = tn;
        mprev = mn;
    }
    if (lane == 0) g_partial[w] = (double)facc;
}

// ---------------------------------------------------------------------------
__global__ void k_final(float* __restrict__ out)
{
    __shared__ double sd[1024];
    int tid = threadIdx.x;
    double v = 0.0;
    #pragma unroll
    for (int i = 0; i < CNUM / 1024; i++) v += g_partial[tid + i * 1024];
    sd[tid] = v;
    __syncthreads();
    #pragma unroll
    for (int o = 512; o > 0; o >>= 1) {
        if (tid < o) sd[tid] += sd[tid + o];
        __syncthreads();
    }
    if (tid == 0) out[0] = (float)sd[0];
}

// ---------------------------------------------------------------------------
extern "C" void kernel_launch(void* const* d_in, const int* in_sizes, int n_in,
                              void* d_out, int out_size)
{
    const float* ti    = (const float*)d_in[0];
    const int*   mi32  = (const int*)  d_in[1];   // int32 or int64; runtime-detected
    const float* mu    = (const float*)d_in[2];
    const float* alpha = (const float*)d_in[3];
    const float* gamma = (const float*)d_in[4];
    float* out = (float*)d_out;

    int N  = in_sizes[0];
    int CS = (N + CNUM - 1) / CNUM;

    k_prep   <<<(MM * AROW + 255) / 256, 256>>>(alpha, gamma, mi32);
    k_phase1 <<<CNUM / 8, 256>>>(ti, mi32, gamma, N, CS);
    k_phase2a<<<NGROUP, NP>>>();
    k_phase2b<<<1, NP>>>();
    k_phase3 <<<CNUM / 16, 512>>>(ti, mi32, mu, gamma, N, CS);
    k_final  <<<1, 1024>>>(out);
}

// round 12
// speedup vs baseline: 7.4880x; 1.1821x over previous
#include <cuda_runtime.h>
#include <cuda_bf16.h>
#include <math.h>

// Hawkes log-likelihood: hierarchical chunked scan over the linear recurrence
//   H[n,m,k] = exp(-gamma_k * dt_n) * (H[n-1,m,k] + onehot(m_{n-1}))
//   lam_n    = mu_n + sum_{m,k} alpha[k, m_n, m] * gamma_k * H[n,m,k]
//   out      = sum_n log(lam_n)
//
// State layout across a warp: entry idx = lane + 32*j (j<7), padded to 224.
//   k = idx & 3  == lane & 3   (one exp per lane per event)
//   m = idx >> 2 == (lane>>2) + 8*j

#define MM     50
#define KK     4
#define NP     224          // padded state entries (200 used)
#define AROW   224          // alphaG row stride
#define CNUM   8192         // chunks
#define GROUP  64           // chunks per scan group
#define NGROUP (CNUM / GROUP)   // 128
#define BROW   232          // transfer row: 224 B + 4 A + pad
#define B2A    16           // phase2a register batch
#define B2B    32           // phase2b register batch
#define EMAX   28           // max events per chunk supported by phase3 tile (CS=25 here)
#define TROW   36           // transpose tile row stride in floats (odd*4, 16B aligned)
#define W3     16           // warps per phase3 block

__device__ __align__(16) float  g_alphaG[MM * AROW];   // [m'][m*4+k] = alpha[k,m',m]*gamma[k]
__device__ __align__(16) float  g_B[CNUM * BROW];      // per-chunk transfer
__device__ __align__(16) float  g_Apre[CNUM * 4];      // A-prefix within group, per k
__device__ __align__(16) float  g_GB[NGROUP * BROW];   // per-group transfer
__device__ __align__(16) float  g_gc[NGROUP * NP];     // group carry-in
__device__ __align__(16) float  g_carry[CNUM * NP];    // local (in-group) prefix per chunk
__device__ double g_partial[CNUM];

// mi dtype detect, inline per warp: if mi is int64 (values < 50), odd words are 0.
__device__ __forceinline__ int detect_shift(const int* __restrict__ mi32, int lane)
{
    int odd = mi32[2 * lane + 1];
    unsigned b = __ballot_sync(0xffffffffu, odd != 0);
    return (b == 0u) ? 1 : 0;
}

// ---------------------------------------------------------------------------
// Phase 1: per-chunk transfer (A per k, B per (m,k)). Warp per chunk.
// ---------------------------------------------------------------------------
__global__ void __launch_bounds__(256) k_phase1(
        const float* __restrict__ ti,
        const int*   __restrict__ mi32,
        const float* __restrict__ gamma,
        int N, int CS)
{
    int w    = (blockIdx.x * blockDim.x + threadIdx.x) >> 5;
    int lane = threadIdx.x & 31;
    if (w >= CNUM) return;
    float* Brow = &g_B[w * BROW];

    const int shift = detect_shift(mi32, lane);

    long s = (long)w * CS;
    int  e = (int)min((long)N, s + CS);
    if (s >= N) {                       // identity transfer
        #pragma unroll
        for (int j = 0; j < 7; j++) Brow[lane + 32 * j] = 0.f;
        if (lane < 4) Brow[NP + lane] = 1.f;
        return;
    }

    const float gk  = gamma[lane & 3];
    const int mbase = lane >> 2;

    float S[7];
    #pragma unroll
    for (int j = 0; j < 7; j++) S[j] = 0.f;

    float tprev = (s > 0) ? ti[s - 1] : ti[0];
    int   mprev = (s > 0) ? mi32[(s - 1) << shift] : -1;
    const float t0 = tprev;

    for (int n = (int)s; n < e; n++) {
        float tn = ti[n];
        float a  = __expf(-gk * (tn - tprev));
        #pragma unroll
        for (int j = 0; j < 7; j++)
            S[j] = fmaf(a, S[j], (mprev == mbase + 8 * j) ? a : 0.f);
        tprev = tn;
        mprev = mi32[n << shift];
    }

    #pragma unroll
    for (int j = 0; j < 7; j++) Brow[lane + 32 * j] = S[j];
    if (lane < 4) Brow[NP + lane] = __expf(-gamma[lane] * (tprev - t0));
}

// ---------------------------------------------------------------------------
// Phase 2a: per-group scan (register-batched loads) + alphaG prep (folded in).
// ---------------------------------------------------------------------------
__global__ void __launch_bounds__(NP) k_phase2a(
        const float* __restrict__ alpha,
        const float* __restrict__ gamma)
{
    int g   = blockIdx.x;
    int tid = threadIdx.x;          // 224
    int k   = tid & 3;
    int c0  = g * GROUP;

    // alphaG prep: one element per thread across the grid (128*224 >= 11200)
    {
        int i = g * NP + tid;
        if (i < MM * AROW) {
            int mp = i / AROW;
            int r  = i % AROW;
            float v = 0.f;
            if (r < MM * KK) {
                int m = r >> 2, kk = r & 3;
                v = alpha[kk * (MM * MM) + mp * MM + m] * gamma[kk];
            }
            g_alphaG[i] = v;
        }
    }

    float carry = 0.f;
    float Aprod = 1.f;

    #pragma unroll 1
    for (int t = 0; t < GROUP; t += B2A) {
        float Av[B2A], Bv[B2A];
        #pragma unroll
        for (int i = 0; i < B2A; i++) {
            int ch = c0 + t + i;
            Av[i] = g_B[ch * BROW + NP + k];
            Bv[i] = g_B[ch * BROW + tid];
        }
        #pragma unroll
        for (int i = 0; i < B2A; i++) {
            int ch = c0 + t + i;
            g_carry[ch * NP + tid] = carry;
            if (tid < 4) g_Apre[ch * 4 + tid] = Aprod;
            carry = fmaf(Av[i], carry, Bv[i]);
            Aprod *= Av[i];
        }
    }
    g_GB[g * BROW + tid] = carry;
    if (tid < 4) g_GB[g * BROW + NP + tid] = Aprod;
}

// ---------------------------------------------------------------------------
// Phase 2b: scan the group transfers (single block, register-batched).
// ---------------------------------------------------------------------------
__global__ void __launch_bounds__(NP) k_phase2b()
{
    int tid = threadIdx.x;          // 224
    int k   = tid & 3;
    float carry = 0.f;

    #pragma unroll 1
    for (int t = 0; t < NGROUP; t += B2B) {
        float Av[B2B], Bv[B2B];
        #pragma unroll
        for (int i = 0; i < B2B; i++) {
            int g = t + i;
            Av[i] = g_GB[g * BROW + NP + k];
            Bv[i] = g_GB[g * BROW + tid];
        }
        #pragma unroll
        for (int i = 0; i < B2B; i++) {
            int g = t + i;
            g_gc[g * NP + tid] = carry;
            carry = fmaf(Av[i], carry, Bv[i]);
        }
    }
}

// ---------------------------------------------------------------------------
// Phase 3: replay with fixed-up carry. Deferred reduction: pass A stores each
// event's per-lane partial dot into a smem tile row; pass B re-reduces with
// lane e owning event e (8x LDS.128 + tree adds + one log per lane), then a
// single butterfly per chunk. Dynamic smem: alphaG + per-warp tiles.
// ---------------------------------------------------------------------------
__global__ void __launch_bounds__(32 * W3) k_phase3(
        const float* __restrict__ ti,
        const int*   __restrict__ mi32,
        const float* __restrict__ mu,
        const float* __restrict__ gamma,
        int N, int CS)
{
    extern __shared__ __align__(16) float dyn[];
    float* sA = dyn;                               // MM*AROW floats
    {
        for (int i = threadIdx.x; i < MM * AROW; i += blockDim.x)
            sA[i] = g_alphaG[i];
    }
    __syncthreads();

    int wid  = threadIdx.x >> 5;
    int lane = threadIdx.x & 31;
    int w    = blockIdx.x * W3 + wid;
    if (w >= CNUM) return;

    float* sT = dyn + MM * AROW + wid * (EMAX * TROW);   // tile: rows=events

    const int shift = detect_shift(mi32, lane);

    long s = (long)w * CS;
    int  e = (int)min((long)N, s + CS);
    if (s >= N) {
        if (lane == 0) g_partial[w] = 0.0;
        return;
    }
    const int cnt = e - (int)s;      // <= EMAX

    const float gk  = gamma[lane & 3];
    const int mbase = lane >> 2;
    const int grp   = w / GROUP;

    // carry fixup: S = Apre * group_carry + local_prefix
    const float Apre = g_Apre[w * 4 + (lane & 3)];
    float S[7];
    #pragma unroll
    for (int j = 0; j < 7; j++)
        S[j] = fmaf(Apre, g_gc[grp * NP + lane + 32 * j],
                    g_carry[w * NP + lane + 32 * j]);

    float tprev = (s > 0) ? ti[s - 1] : ti[0];
    int   mprev = (s > 0) ? mi32[(s - 1) << shift] : -1;

    // Pass A: recurrence + per-lane partial dot -> smem tile (no reduction)
    for (int q = 0; q < cnt; q++) {
        int   n  = (int)s + q;
        float tn = ti[n];
        int   mn = mi32[n << shift];
        float a  = __expf(-gk * (tn - tprev));
        #pragma unroll
        for (int j = 0; j < 7; j++)
            S[j] = fmaf(a, S[j], (mprev == mbase + 8 * j) ? a : 0.f);

        const float* row = &sA[mn * AROW];
        float dot = 0.f;
        #pragma unroll
        for (int j = 0; j < 7; j++)
            dot = fmaf(row[lane + 32 * j], S[j], dot);

        sT[q * TROW + lane] = dot;
        tprev = tn;
        mprev = mn;
    }
    __syncwarp();

    // Pass B: lane q reduces event q's 32 partials (fixed order) + log
    float val = 0.f;
    if (lane < cnt) {
        const float4* r4 = (const float4*)&sT[lane * TROW];
        float4 v0 = r4[0], v1 = r4[1], v2 = r4[2], v3 = r4[3];
        float4 v4 = r4[4], v5 = r4[5], v6 = r4[6], v7 = r4[7];
        float s0 = ((v0.x + v0.y) + (v0.z + v0.w)) + ((v1.x + v1.y) + (v1.z + v1.w));
        float s1 = ((v2.x + v2.y) + (v2.z + v2.w)) + ((v3.x + v3.y) + (v3.z + v3.w));
        float s2 = ((v4.x + v4.y) + (v4.z + v4.w)) + ((v5.x + v5.y) + (v5.z + v5.w));
        float s3 = ((v6.x + v6.y) + (v6.z + v6.w)) + ((v7.x + v7.y) + (v7.z + v7.w));
        float sum = (s0 + s1) + (s2 + s3);
        val = __logf(mu[(int)s + lane] + sum);
    }

    // one butterfly per chunk
    #pragma unroll
    for (int o = 16; o > 0; o >>= 1)
        val += __shfl_xor_sync(0xffffffffu, val, o);

    if (lane == 0) g_partial[w] = (double)val;
}

// ---------------------------------------------------------------------------
__global__ void k_final(float* __restrict__ out)
{
    __shared__ double sd[1024];
    int tid = threadIdx.x;
    double v = 0.0;
    #pragma unroll
    for (int i = 0; i < CNUM / 1024; i++) v += g_partial[tid + i * 1024];
    sd[tid] = v;
    __syncthreads();
    #pragma unroll
    for (int o = 512; o > 0; o >>= 1) {
        if (tid < o) sd[tid] += sd[tid + o];
        __syncthreads();
    }
    if (tid == 0) out[0] = (float)sd[0];
}

// ---------------------------------------------------------------------------
extern "C" void kernel_launch(void* const* d_in, const int* in_sizes, int n_in,
                              void* d_out, int out_size)
{
    const float* ti    = (const float*)d_in[0];
    const int*   mi32  = (const int*)  d_in[1];   // int32 or int64; runtime-detected
    const float* mu    = (const float*)d_in[2];
    const float* alpha = (const float*)d_in[3];
    const float* gamma = (const float*)d_in[4];
    float* out = (float*)d_out;

    int N  = in_sizes[0];
    int CS = (N + CNUM - 1) / CNUM;   // 25 for N=200000 (<= EMAX required)

    const int P3_SMEM = (MM * AROW + W3 * EMAX * TROW) * 4;   // 109312 B
    cudaFuncSetAttribute(k_phase3, cudaFuncAttributeMaxDynamicSharedMemorySize, P3_SMEM);

    k_phase1 <<<CNUM / 8, 256>>>(ti, mi32, gamma, N, CS);
    k_phase2a<<<NGROUP, NP>>>(alpha, gamma);
    k_phase2b<<<1, NP>>>();
    k_phase3 <<<CNUM / W3, 32 * W3, P3_SMEM>>>(ti, mi32, mu, gamma, N, CS);
    k_final  <<<1, 1024>>>(out);
}

// round 13
// speedup vs baseline: 12.2909x; 1.6414x over previous
#include <cuda_runtime.h>
#include <cuda_bf16.h>
#include <math.h>

// Hawkes log-likelihood: hierarchical chunked scan over the linear recurrence
//   H[n,m,k] = exp(-gamma_k * dt_n) * (H[n-1,m,k] + onehot(m_{n-1}))
//   lam_n    = mu_n + sum_{m,k} alpha[k, m_n, m] * gamma_k * H[n,m,k]
//   out      = sum_n log(lam_n)
//
// State layout across a warp: entry idx = lane + 32*j (j<7).
//   k = idx & 3 == lane & 3,  m = idx >> 2 == (lane>>2) + 8*j
//
// alphaG rows are stored in per-lane float4 groups so the 7-term dot is
// 2x LDS.128: row'[lane*4+u]     = orig[lane + 32*u]   (u=0..3)
//             row'[128+lane*4+u] = orig[lane + 32*(u+4)] (u=0..2, u=3 pad)

#define MM     50
#define KK     4
#define NP     224          // state entries (200 used, padded)
#define AR2    256          // alphaG row stride in floats (64 float4)
#define CNUM   8192         // chunks
#define GROUP  64           // chunks per scan group
#define NGROUP (CNUM / GROUP)   // 128
#define BROW   232          // transfer row: 224 B + 4 A + pad
#define B2A    32           // phase2a register batch
#define B2B    32           // phase2b register batch
#define EMAX   26           // max events/chunk in phase3 tile (CS=25 here; CS<=EMAX<=31 required)
#define TROW   36           // transpose tile row stride (floats, 16B aligned)
#define W3     16           // warps per phase3 block

__device__ __align__(16) float  g_alphaG[MM * AR2];    // packed layout above
__device__ __align__(16) float  g_B[CNUM * BROW];      // per-chunk transfer
__device__ __align__(16) float  g_Apre[CNUM * 4];      // A-prefix within group, per k
__device__ __align__(16) float  g_GB[NGROUP * BROW];   // per-group transfer
__device__ __align__(16) float  g_gc[NGROUP * NP];     // group carry-in
__device__ __align__(16) float  g_carry[CNUM * NP];    // local (in-group) prefix
__device__ double g_partial[CNUM];

// mi dtype detect, inline per warp: if mi is int64 (values < 50), odd words are 0.
__device__ __forceinline__ int detect_shift(const int* __restrict__ mi32, int lane)
{
    int odd = mi32[2 * lane + 1];
    unsigned b = __ballot_sync(0xffffffffu, odd != 0);
    return (b == 0u) ? 1 : 0;
}

// ---------------------------------------------------------------------------
// Phase 1: per-chunk transfer (A per k, B per (m,k)). Warp per chunk.
// ti/mi preloaded into lane registers, broadcast via shfl in the loop.
// ---------------------------------------------------------------------------
__global__ void __launch_bounds__(256) k_phase1(
        const float* __restrict__ ti,
        const int*   __restrict__ mi32,
        const float* __restrict__ gamma,
        int N, int CS)
{
    int w    = (blockIdx.x * blockDim.x + threadIdx.x) >> 5;
    int lane = threadIdx.x & 31;
    if (w >= CNUM) return;
    float* Brow = &g_B[w * BROW];

    const int shift = detect_shift(mi32, lane);

    long s = (long)w * CS;
    int  e = (int)min((long)N, s + CS);
    if (s >= N) {                       // identity transfer
        #pragma unroll
        for (int j = 0; j < 7; j++) Brow[lane + 32 * j] = 0.f;
        if (lane < 4) Brow[NP + lane] = 1.f;
        return;
    }
    const int cnt = e - (int)s;

    // preload: lane q holds ti/mi at index s-1+q (clamped)
    long li = s - 1 + lane;
    if (li < 0) li = 0;
    if (li > N - 1) li = N - 1;
    float tload = ti[li];
    int   mload = mi32[li << shift];

    const float gk  = gamma[lane & 3];
    const int mbase = lane >> 2;

    float S[7];
    #pragma unroll
    for (int j = 0; j < 7; j++) S[j] = 0.f;

    float tprev = __shfl_sync(0xffffffffu, tload, 0);
    int   mprev = (s > 0) ? __shfl_sync(0xffffffffu, mload, 0) : -1;
    const float t0 = tprev;

    for (int q = 0; q < cnt; q++) {
        float tn = __shfl_sync(0xffffffffu, tload, q + 1);
        int   mn = __shfl_sync(0xffffffffu, mload, q + 1);
        float a  = __expf(-gk * (tn - tprev));
        #pragma unroll
        for (int j = 0; j < 7; j++)
            S[j] = fmaf(a, S[j], (mprev == mbase + 8 * j) ? a : 0.f);
        tprev = tn;
        mprev = mn;
    }

    #pragma unroll
    for (int j = 0; j < 7; j++) Brow[lane + 32 * j] = S[j];
    if (lane < 4) Brow[NP + lane] = __expf(-gamma[lane] * (tprev - t0));
}

// ---------------------------------------------------------------------------
// Phase 2a: per-group scan (register-batched loads) + alphaG prep (folded in).
// ---------------------------------------------------------------------------
__global__ void __launch_bounds__(NP) k_phase2a(
        const float* __restrict__ alpha,
        const float* __restrict__ gamma)
{
    int g   = blockIdx.x;
    int tid = threadIdx.x;          // 224
    int k   = tid & 3;
    int c0  = g * GROUP;

    // alphaG prep in packed layout: one element per thread (128*224 >= 12800)
    {
        int i = g * NP + tid;
        if (i < MM * AR2) {
            int mp = i / AR2;
            int p  = i % AR2;
            int l, u;
            if (p < 128) { l = p >> 2;        u = p & 3; }
            else         { l = (p - 128) >> 2; u = (p & 3) + 4; }
            int c = l + 32 * u;              // original column = lane + 32*j
            float v = 0.f;
            if (u < 7 && c < MM * KK) {
                int m = c >> 2, kk = c & 3;
                v = alpha[kk * (MM * MM) + mp * MM + m] * gamma[kk];
            }
            g_alphaG[i] = v;
        }
    }

    float carry = 0.f;
    float Aprod = 1.f;

    #pragma unroll 1
    for (int t = 0; t < GROUP; t += B2A) {
        float Av[B2A], Bv[B2A];
        #pragma unroll
        for (int i = 0; i < B2A; i++) {
            int ch = c0 + t + i;
            Av[i] = g_B[ch * BROW + NP + k];
            Bv[i] = g_B[ch * BROW + tid];
        }
        #pragma unroll
        for (int i = 0; i < B2A; i++) {
            int ch = c0 + t + i;
            g_carry[ch * NP + tid] = carry;
            if (tid < 4) g_Apre[ch * 4 + tid] = Aprod;
            carry = fmaf(Av[i], carry, Bv[i]);
            Aprod *= Av[i];
        }
    }
    g_GB[g * BROW + tid] = carry;
    if (tid < 4) g_GB[g * BROW + NP + tid] = Aprod;
}

// ---------------------------------------------------------------------------
// Phase 2b: scan the group transfers (single block, register-batched).
// ---------------------------------------------------------------------------
__global__ void __launch_bounds__(NP) k_phase2b()
{
    int tid = threadIdx.x;          // 224
    int k   = tid & 3;
    float carry = 0.f;

    #pragma unroll 1
    for (int t = 0; t < NGROUP; t += B2B) {
        float Av[B2B], Bv[B2B];
        #pragma unroll
        for (int i = 0; i < B2B; i++) {
            int g = t + i;
            Av[i] = g_GB[g * BROW + NP + k];
            Bv[i] = g_GB[g * BROW + tid];
        }
        #pragma unroll
        for (int i = 0; i < B2B; i++) {
            int g = t + i;
            g_gc[g * NP + tid] = carry;
            carry = fmaf(Av[i], carry, Bv[i]);
        }
    }
}

// ---------------------------------------------------------------------------
// Phase 3: replay with fixed-up carry; deferred reduction via smem transpose
// tile. Dot = 2x LDS.128 from packed alphaG. ti/mi broadcast via shfl.
// ---------------------------------------------------------------------------
__global__ void __launch_bounds__(32 * W3) k_phase3(
        const float* __restrict__ ti,
        const int*   __restrict__ mi32,
        const float* __restrict__ mu,
        const float* __restrict__ gamma,
        int N, int CS)
{
    extern __shared__ __align__(16) float dyn[];
    float* sA = dyn;                               // MM*AR2 floats
    for (int i = threadIdx.x; i < MM * AR2; i += blockDim.x)
        sA[i] = g_alphaG[i];
    __syncthreads();

    int wid  = threadIdx.x >> 5;
    int lane = threadIdx.x & 31;
    int w    = blockIdx.x * W3 + wid;
    if (w >= CNUM) return;

    float* sT = dyn + MM * AR2 + wid * (EMAX * TROW);   // tile: rows=events

    const int shift = detect_shift(mi32, lane);

    long s = (long)w * CS;
    int  e = (int)min((long)N, s + CS);
    if (s >= N) {
        if (lane == 0) g_partial[w] = 0.0;
        return;
    }
    const int cnt = e - (int)s;      // <= EMAX

    // preload ti/mi: lane q holds index s-1+q (clamped)
    long li = s - 1 + lane;
    if (li < 0) li = 0;
    if (li > N - 1) li = N - 1;
    float tload = ti[li];
    int   mload = mi32[li << shift];

    const float gk  = gamma[lane & 3];
    const int mbase = lane >> 2;
    const int grp   = w / GROUP;

    // carry fixup: S = Apre * group_carry + local_prefix
    const float Apre = g_Apre[w * 4 + (lane & 3)];
    float S[7];
    #pragma unroll
    for (int j = 0; j < 7; j++)
        S[j] = fmaf(Apre, g_gc[grp * NP + lane + 32 * j],
                    g_carry[w * NP + lane + 32 * j]);

    float tprev = __shfl_sync(0xffffffffu, tload, 0);
    int   mprev = (s > 0) ? __shfl_sync(0xffffffffu, mload, 0) : -1;

    // Pass A: recurrence + per-lane partial dot -> smem tile
    for (int q = 0; q < cnt; q++) {
        float tn = __shfl_sync(0xffffffffu, tload, q + 1);
        int   mn = __shfl_sync(0xffffffffu, mload, q + 1);
        float a  = __expf(-gk * (tn - tprev));
        #pragma unroll
        for (int j = 0; j < 7; j++)
            S[j] = fmaf(a, S[j], (mprev == mbase + 8 * j) ? a : 0.f);

        const float4* rb = (const float4*)(sA + mn * AR2);
        float4 va = rb[lane];
        float4 vb = rb[32 + lane];
        float dot = va.x * S[0];
        dot = fmaf(va.y, S[1], dot);
        dot = fmaf(va.z, S[2], dot);
        dot = fmaf(va.w, S[3], dot);
        dot = fmaf(vb.x, S[4], dot);
        dot = fmaf(vb.y, S[5], dot);
        dot = fmaf(vb.z, S[6], dot);

        sT[q * TROW + lane] = dot;
        tprev = tn;
        mprev = mn;
    }
    __syncwarp();

    // Pass B: lane q reduces event q's 32 partials (fixed order) + log
    float val = 0.f;
    if (lane < cnt) {
        const float4* r4 = (const float4*)&sT[lane * TROW];
        float4 v0 = r4[0], v1 = r4[1], v2 = r4[2], v3 = r4[3];
        float4 v4 = r4[4], v5 = r4[5], v6 = r4[6], v7 = r4[7];
        float s0 = ((v0.x + v0.y) + (v0.z + v0.w)) + ((v1.x + v1.y) + (v1.z + v1.w));
        float s1 = ((v2.x + v2.y) + (v2.z + v2.w)) + ((v3.x + v3.y) + (v3.z + v3.w));
        float s2 = ((v4.x + v4.y) + (v4.z + v4.w)) + ((v5.x + v5.y) + (v5.z + v5.w));
        float s3 = ((v6.x + v6.y) + (v6.z + v6.w)) + ((v7.x + v7.y) + (v7.z + v7.w));
        float sum = (s0 + s1) + (s2 + s3);
        val = __logf(mu[(int)s + lane] + sum);
    }

    #pragma unroll
    for (int o = 16; o > 0; o >>= 1)
        val += __shfl_xor_sync(0xffffffffu, val, o);

    if (lane == 0) g_partial[w] = (double)val;
}

// ---------------------------------------------------------------------------
__global__ void k_final(float* __restrict__ out)
{
    __shared__ double sd[1024];
    int tid = threadIdx.x;
    double v = 0.0;
    #pragma unroll
    for (int i = 0; i < CNUM / 1024; i++) v += g_partial[tid + i * 1024];
    sd[tid] = v;
    __syncthreads();
    #pragma unroll
    for (int o = 512; o > 0; o >>= 1) {
        if (tid < o) sd[tid] += sd[tid + o];
        __syncthreads();
    }
    if (tid == 0) out[0] = (float)sd[0];
}

// ---------------------------------------------------------------------------
extern "C" void kernel_launch(void* const* d_in, const int* in_sizes, int n_in,
                              void* d_out, int out_size)
{
    const float* ti    = (const float*)d_in[0];
    const int*   mi32  = (const int*)  d_in[1];   // int32 or int64; runtime-detected
    const float* mu    = (const float*)d_in[2];
    const float* alpha = (const float*)d_in[3];
    const float* gamma = (const float*)d_in[4];
    float* out = (float*)d_out;

    int N  = in_sizes[0];
    int CS = (N + CNUM - 1) / CNUM;   // 25 for N=200000 (must be <= EMAX)

    const int P3_SMEM = (MM * AR2 + W3 * EMAX * TROW) * 4;   // 111104 B -> 2 blocks/SM
    cudaFuncSetAttribute(k_phase3, cudaFuncAttributeMaxDynamicSharedMemorySize, P3_SMEM);

    k_phase1 <<<CNUM / 8, 256>>>(ti, mi32, gamma, N, CS);
    k_phase2a<<<NGROUP, NP>>>(alpha, gamma);
    k_phase2b<<<1, NP>>>();
    k_phase3 <<<CNUM / W3, 32 * W3, P3_SMEM>>>(ti, mi32, mu, gamma, N, CS);
    k_final  <<<1, 1024>>>(out);
}

// round 14
// speedup vs baseline: 12.7702x; 1.0390x over previous
#include <cuda_runtime.h>
#include <cuda_bf16.h>
#include <math.h>

// Hawkes log-likelihood: hierarchical chunked scan over the linear recurrence
//   H[n,m,k] = exp(-gamma_k * dt_n) * (H[n-1,m,k] + onehot(m_{n-1}))
//   lam_n    = mu_n + sum_{m,k} alpha[k, m_n, m] * gamma_k * H[n,m,k]
//   out      = sum_n log(lam_n)
//
// State layout across a warp: entry idx = lane + 32*j (j<7).
//   k = idx & 3 == lane & 3,  m = idx >> 2 == (lane>>2) + 8*j
//
// Per-chunk exp batching: dt depends only on ti, so lane q evaluates all 4
// exp(-gamma_k*dt_q) upfront (4 MUFU warp-ops per chunk instead of ~25); the
// event loop reads its a via one broadcast LDS from the tile row pad.

#define MM     50
#define KK     4
#define NP     224          // state entries (200 used, padded)
#define AR2    256          // alphaG row stride in floats (64 float4)
#define CNUM   8192         // chunks
#define GROUP  64           // chunks per scan group
#define NGROUP (CNUM / GROUP)   // 128
#define BROW   232          // transfer row: 224 B + 4 A + pad
#define B2A    32           // phase2a register batch
#define B2B    32           // phase2b register batch
#define EMAX   26           // max events/chunk in phase3 tile (CS=25 here)
#define TROW   36           // tile row stride (floats): 32 dots + 4 a-values (16B aligned)
#define W3     16           // warps per phase3 block

__device__ __align__(16) float  g_alphaG[MM * AR2];    // packed layout above
__device__ __align__(16) float  g_B[CNUM * BROW];      // per-chunk transfer
__device__ __align__(16) float  g_Apre[CNUM * 4];      // A-prefix within group, per k
__device__ __align__(16) float  g_GB[NGROUP * BROW];   // per-group transfer
__device__ __align__(16) float  g_gc[NGROUP * NP];     // group carry-in
__device__ __align__(16) float  g_carry[CNUM * NP];    // local (in-group) prefix
__device__ double g_partial[CNUM];

// mi dtype detect, inline per warp: if mi is int64 (values < 50), odd words are 0.
__device__ __forceinline__ int detect_shift(const int* __restrict__ mi32, int lane)
{
    int odd = mi32[2 * lane + 1];
    unsigned b = __ballot_sync(0xffffffffu, odd != 0);
    return (b == 0u) ? 1 : 0;
}

// ---------------------------------------------------------------------------
// Phase 1: per-chunk transfer (A per k, B per (m,k)). Warp per chunk.
// ---------------------------------------------------------------------------
__global__ void __launch_bounds__(256) k_phase1(
        const float* __restrict__ ti,
        const int*   __restrict__ mi32,
        const float* __restrict__ gamma,
        int N, int CS)
{
    __shared__ __align__(16) float sP[8][EMAX * 4];   // per-warp a-tiles

    int wid  = threadIdx.x >> 5;
    int lane = threadIdx.x & 31;
    int w    = blockIdx.x * 8 + wid;
    if (w >= CNUM) return;
    float* Brow = &g_B[w * BROW];

    const int shift = detect_shift(mi32, lane);

    long s = (long)w * CS;
    int  e = (int)min((long)N, s + CS);
    if (s >= N) {                       // identity transfer
        #pragma unroll
        for (int j = 0; j < 7; j++) Brow[lane + 32 * j] = 0.f;
        if (lane < 4) Brow[NP + lane] = 1.f;
        return;
    }
    const int cnt = e - (int)s;

    // preload: lane q holds ti/mi at index s-1+q (clamped)
    long li = s - 1 + lane;
    if (li < 0) li = 0;
    if (li > N - 1) li = N - 1;
    float tload = ti[li];
    int   mload = mi32[li << shift];

    const float4 g4 = *(const float4*)gamma;

    // batch exps: lane q -> a[q][k] for event q
    {
        float tnext = __shfl_down_sync(0xffffffffu, tload, 1);
        float dtq   = tnext - tload;
        if (lane < cnt) {
            float4 av;
            av.x = __expf(-g4.x * dtq);
            av.y = __expf(-g4.y * dtq);
            av.z = __expf(-g4.z * dtq);
            av.w = __expf(-g4.w * dtq);
            *(float4*)&sP[wid][lane * 4] = av;
        }
    }
    __syncwarp();

    const int kidx  = lane & 3;
    const int mbase = lane >> 2;

    float S[7];
    #pragma unroll
    for (int j = 0; j < 7; j++) S[j] = 0.f;

    int mprev = (s > 0) ? __shfl_sync(0xffffffffu, mload, 0) : -1;

    #pragma unroll 5
    for (int q = 0; q < cnt; q++) {
        int   mn = __shfl_sync(0xffffffffu, mload, q + 1);
        float a  = sP[wid][q * 4 + kidx];
        #pragma unroll
        for (int j = 0; j < 7; j++)
            S[j] = fmaf(a, S[j], (mprev == mbase + 8 * j) ? a : 0.f);
        mprev = mn;
    }

    #pragma unroll
    for (int j = 0; j < 7; j++) Brow[lane + 32 * j] = S[j];

    float t0    = __shfl_sync(0xffffffffu, tload, 0);
    float tlast = __shfl_sync(0xffffffffu, tload, cnt);
    if (lane < 4) Brow[NP + lane] = __expf(-gamma[lane] * (tlast - t0));
}

// ---------------------------------------------------------------------------
// Phase 2a: per-group scan (register-batched loads) + alphaG prep (folded in).
// ---------------------------------------------------------------------------
__global__ void __launch_bounds__(NP) k_phase2a(
        const float* __restrict__ alpha,
        const float* __restrict__ gamma)
{
    int g   = blockIdx.x;
    int tid = threadIdx.x;          // 224
    int k   = tid & 3;
    int c0  = g * GROUP;

    // alphaG prep in packed layout: one element per thread (128*224 >= 12800)
    {
        int i = g * NP + tid;
        if (i < MM * AR2) {
            int mp = i / AR2;
            int p  = i % AR2;
            int l, u;
            if (p < 128) { l = p >> 2;        u = p & 3; }
            else         { l = (p - 128) >> 2; u = (p & 3) + 4; }
            int c = l + 32 * u;              // original column = lane + 32*j
            float v = 0.f;
            if (u < 7 && c < MM * KK) {
                int m = c >> 2, kk = c & 3;
                v = alpha[kk * (MM * MM) + mp * MM + m] * gamma[kk];
            }
            g_alphaG[i] = v;
        }
    }

    float carry = 0.f;
    float Aprod = 1.f;

    #pragma unroll 1
    for (int t = 0; t < GROUP; t += B2A) {
        float Av[B2A], Bv[B2A];
        #pragma unroll
        for (int i = 0; i < B2A; i++) {
            int ch = c0 + t + i;
            Av[i] = g_B[ch * BROW + NP + k];
            Bv[i] = g_B[ch * BROW + tid];
        }
        #pragma unroll
        for (int i = 0; i < B2A; i++) {
            int ch = c0 + t + i;
            g_carry[ch * NP + tid] = carry;
            if (tid < 4) g_Apre[ch * 4 + tid] = Aprod;
            carry = fmaf(Av[i], carry, Bv[i]);
            Aprod *= Av[i];
        }
    }
    g_GB[g * BROW + tid] = carry;
    if (tid < 4) g_GB[g * BROW + NP + tid] = Aprod;
}

// ---------------------------------------------------------------------------
// Phase 2b: scan the group transfers (single block, register-batched).
// ---------------------------------------------------------------------------
__global__ void __launch_bounds__(NP) k_phase2b()
{
    int tid = threadIdx.x;          // 224
    int k   = tid & 3;
    float carry = 0.f;

    #pragma unroll 1
    for (int t = 0; t < NGROUP; t += B2B) {
        float Av[B2B], Bv[B2B];
        #pragma unroll
        for (int i = 0; i < B2B; i++) {
            int g = t + i;
            Av[i] = g_GB[g * BROW + NP + k];
            Bv[i] = g_GB[g * BROW + tid];
        }
        #pragma unroll
        for (int i = 0; i < B2B; i++) {
            int g = t + i;
            g_gc[g * NP + tid] = carry;
            carry = fmaf(Av[i], carry, Bv[i]);
        }
    }
}

// ---------------------------------------------------------------------------
// Phase 3: replay with fixed-up carry; deferred reduction via smem transpose
// tile. Batched exps live in the tile row pad. Dot = 2x LDS.128.
// ---------------------------------------------------------------------------
__global__ void __launch_bounds__(32 * W3) k_phase3(
        const float* __restrict__ ti,
        const int*   __restrict__ mi32,
        const float* __restrict__ mu,
        const float* __restrict__ gamma,
        int N, int CS)
{
    extern __shared__ __align__(16) float dyn[];
    float* sA = dyn;                               // MM*AR2 floats
    for (int i = threadIdx.x; i < MM * AR2; i += blockDim.x)
        sA[i] = g_alphaG[i];
    __syncthreads();

    int wid  = threadIdx.x >> 5;
    int lane = threadIdx.x & 31;
    int w    = blockIdx.x * W3 + wid;
    if (w >= CNUM) return;

    float* sT = dyn + MM * AR2 + wid * (EMAX * TROW);   // rows=events; pad = a[4]

    const int shift = detect_shift(mi32, lane);

    long s = (long)w * CS;
    int  e = (int)min((long)N, s + CS);
    if (s >= N) {
        if (lane == 0) g_partial[w] = 0.0;
        return;
    }
    const int cnt = e - (int)s;      // <= EMAX

    // preload ti/mi: lane q holds index s-1+q (clamped)
    long li = s - 1 + lane;
    if (li < 0) li = 0;
    if (li > N - 1) li = N - 1;
    float tload = ti[li];
    int   mload = mi32[li << shift];

    const float4 g4 = *(const float4*)gamma;

    // batch exps into row pads: lane q -> sT[q*TROW+32..35]
    {
        float tnext = __shfl_down_sync(0xffffffffu, tload, 1);
        float dtq   = tnext - tload;
        if (lane < cnt) {
            float4 av;
            av.x = __expf(-g4.x * dtq);
            av.y = __expf(-g4.y * dtq);
            av.z = __expf(-g4.z * dtq);
            av.w = __expf(-g4.w * dtq);
            *(float4*)&sT[lane * TROW + 32] = av;
        }
    }
    __syncwarp();

    const int kidx  = lane & 3;
    const int mbase = lane >> 2;
    const int grp   = w / GROUP;

    // carry fixup: S = Apre * group_carry + local_prefix
    const float Apre = g_Apre[w * 4 + kidx];
    float S[7];
    #pragma unroll
    for (int j = 0; j < 7; j++)
        S[j] = fmaf(Apre, g_gc[grp * NP + lane + 32 * j],
                    g_carry[w * NP + lane + 32 * j]);

    int mprev = (s > 0) ? __shfl_sync(0xffffffffu, mload, 0) : -1;

    // Pass A: recurrence + per-lane partial dot -> smem tile
    #pragma unroll 5
    for (int q = 0; q < cnt; q++) {
        int   mn = __shfl_sync(0xffffffffu, mload, q + 1);
        float a  = sT[q * TROW + 32 + kidx];
        #pragma unroll
        for (int j = 0; j < 7; j++)
            S[j] = fmaf(a, S[j], (mprev == mbase + 8 * j) ? a : 0.f);

        const float4* rb = (const float4*)(sA + mn * AR2);
        float4 va = rb[lane];
        float4 vb = rb[32 + lane];
        float dot = va.x * S[0];
        dot = fmaf(va.y, S[1], dot);
        dot = fmaf(va.z, S[2], dot);
        dot = fmaf(va.w, S[3], dot);
        dot = fmaf(vb.x, S[4], dot);
        dot = fmaf(vb.y, S[5], dot);
        dot = fmaf(vb.z, S[6], dot);

        sT[q * TROW + lane] = dot;
        mprev = mn;
    }
    __syncwarp();

    // Pass B: lane q reduces event q's 32 partials (fixed order) + log
    float val = 0.f;
    if (lane < cnt) {
        const float4* r4 = (const float4*)&sT[lane * TROW];
        float4 v0 = r4[0], v1 = r4[1], v2 = r4[2], v3 = r4[3];
        float4 v4 = r4[4], v5 = r4[5], v6 = r4[6], v7 = r4[7];
        float s0 = ((v0.x + v0.y) + (v0.z + v0.w)) + ((v1.x + v1.y) + (v1.z + v1.w));
        float s1 = ((v2.x + v2.y) + (v2.z + v2.w)) + ((v3.x + v3.y) + (v3.z + v3.w));
        float s2 = ((v4.x + v4.y) + (v4.z + v4.w)) + ((v5.x + v5.y) + (v5.z + v5.w));
        float s3 = ((v6.x + v6.y) + (v6.z + v6.w)) + ((v7.x + v7.y) + (v7.z + v7.w));
        float sum = (s0 + s1) + (s2 + s3);
        val = __logf(mu[(int)s + lane] + sum);
    }

    #pragma unroll
    for (int o = 16; o > 0; o >>= 1)
        val += __shfl_xor_sync(0xffffffffu, val, o);

    if (lane == 0) g_partial[w] = (double)val;
}

// ---------------------------------------------------------------------------
__global__ void k_final(float* __restrict__ out)
{
    __shared__ double sd[1024];
    int tid = threadIdx.x;
    double v = 0.0;
    #pragma unroll
    for (int i = 0; i < CNUM / 1024; i++) v += g_partial[tid + i * 1024];
    sd[tid] = v;
    __syncthreads();
    #pragma unroll
    for (int o = 512; o > 0; o >>= 1) {
        if (tid < o) sd[tid] += sd[tid + o];
        __syncthreads();
    }
    if (tid == 0) out[0] = (float)sd[0];
}

// ---------------------------------------------------------------------------
extern "C" void kernel_launch(void* const* d_in, const int* in_sizes, int n_in,
                              void* d_out, int out_size)
{
    const float* ti    = (const float*)d_in[0];
    const int*   mi32  = (const int*)  d_in[1];   // int32 or int64; runtime-detected
    const float* mu    = (const float*)d_in[2];
    const float* alpha = (const float*)d_in[3];
    const float* gamma = (const float*)d_in[4];
    float* out = (float*)d_out;

    int N  = in_sizes[0];
    int CS = (N + CNUM - 1) / CNUM;   // 25 for N=200000 (must be <= EMAX)

    const int P3_SMEM = (MM * AR2 + W3 * EMAX * TROW) * 4;   // 111104 B -> 2 blocks/SM
    cudaFuncSetAttribute(k_phase3, cudaFuncAttributeMaxDynamicSharedMemorySize, P3_SMEM);

    k_phase1 <<<CNUM / 8, 256>>>(ti, mi32, gamma, N, CS);
    k_phase2a<<<NGROUP, NP>>>(alpha, gamma);
    k_phase2b<<<1, NP>>>();
    k_phase3 <<<CNUM / W3, 32 * W3, P3_SMEM>>>(ti, mi32, mu, gamma, N, CS);
    k_final  <<<1, 1024>>>(out);
}

// round 16
// speedup vs baseline: 13.4937x; 1.0567x over previous
#include <cuda_runtime.h>
#include <cuda_bf16.h>
#include <math.h>

// Hawkes log-likelihood: hierarchical chunked scan over the linear recurrence
//   H[n,m,k] = exp(-gamma_k * dt_n) * (H[n-1,m,k] + onehot(m_{n-1}))
//   lam_n    = mu_n + sum_{m,k} alpha[k, m_n, m] * gamma_k * H[n,m,k]
//   out      = sum_n log(lam_n)
//
// State layout across a warp: entry idx = lane + 32*j (j<7).
//   k = idx & 3 == lane & 3,  m = idx >> 2 == (lane>>2) + 8*j

#define MM     50
#define KK     4
#define NP     224          // state entries (200 used, padded)
#define AR2    256          // alphaG row stride in floats (64 float4)
#define CNUM   8192         // chunks
#define GROUP  64           // chunks per scan group
#define NGROUP (CNUM / GROUP)   // 128
#define BROW   232          // transfer row: 224 B + 4 A + pad
#define B2A    32           // phase2a register batch
#define B2B    32           // phase2b register batch
#define CSFIX  25           // specialized chunk size (N=200000/8192)
#define EMAX   26           // max events/chunk in phase3 tile
#define TROW   36           // tile row stride (floats): 32 dots + 4 a-values
#define W3     16           // warps per phase3 block

__device__ __align__(16) float  g_alphaG[MM * AR2];    // packed layout
__device__ __align__(16) float  g_B[CNUM * BROW];      // per-chunk transfer
__device__ __align__(16) float  g_Apre[CNUM * 4];      // A-prefix within group, per k
__device__ __align__(16) float  g_GB[NGROUP * BROW];   // per-group transfer
__device__ __align__(16) float  g_gc[NGROUP * NP];     // group carry-in
__device__ __align__(16) float  g_carry[CNUM * NP];    // local (in-group) prefix
__device__ double g_partial[CNUM];
__device__ int    g_done = 0;                          // last-block counter (self-reset)

// mi dtype detect, inline per warp: if mi is int64 (values < 50), odd words are 0.
__device__ __forceinline__ int detect_shift(const int* __restrict__ mi32, int lane)
{
    int odd = mi32[2 * lane + 1];
    unsigned b = __ballot_sync(0xffffffffu, odd != 0);
    return (b == 0u) ? 1 : 0;
}

// ---------------------------------------------------------------------------
// Phase 1: per-chunk transfer (A per k, B per (m,k)). Warp per chunk.
// ---------------------------------------------------------------------------
__global__ void __launch_bounds__(256) k_phase1(
        const float* __restrict__ ti,
        const int*   __restrict__ mi32,
        const float* __restrict__ gamma,
        int N, int CS)
{
    __shared__ __align__(16) float sP[8][EMAX * 4];   // per-warp a-tiles

    int wid  = threadIdx.x >> 5;
    int lane = threadIdx.x & 31;
    int w    = blockIdx.x * 8 + wid;
    if (w >= CNUM) return;
    float* Brow = &g_B[w * BROW];

    const int shift = detect_shift(mi32, lane);

    long s = (long)w * CS;
    int  e = (int)min((long)N, s + CS);
    if (s >= N) {                       // identity transfer
        #pragma unroll
        for (int j = 0; j < 7; j++) Brow[lane + 32 * j] = 0.f;
        if (lane < 4) Brow[NP + lane] = 1.f;
        return;
    }
    const int cnt = e - (int)s;

    // preload: lane q holds ti/mi at index s-1+q (clamped)
    long li = s - 1 + lane;
    if (li < 0) li = 0;
    if (li > N - 1) li = N - 1;
    float tload = ti[li];
    int   mload = mi32[li << shift];

    const float4 g4 = *(const float4*)gamma;

    // batch exps: lane q -> a[q][k] for event q
    {
        float tnext = __shfl_down_sync(0xffffffffu, tload, 1);
        float dtq   = tnext - tload;
        if (lane < cnt) {
            float4 av;
            av.x = __expf(-g4.x * dtq);
            av.y = __expf(-g4.y * dtq);
            av.z = __expf(-g4.z * dtq);
            av.w = __expf(-g4.w * dtq);
            *(float4*)&sP[wid][lane * 4] = av;
        }
    }
    __syncwarp();

    const int kidx  = lane & 3;
    const int mbase = lane >> 2;

    float S[7];
    #pragma unroll
    for (int j = 0; j < 7; j++) S[j] = 0.f;

    int mprev = (s > 0) ? __shfl_sync(0xffffffffu, mload, 0) : -1;

    auto body = [&](int q) {
        int   mn = __shfl_sync(0xffffffffu, mload, q + 1);
        float a  = sP[wid][q * 4 + kidx];
        #pragma unroll
        for (int j = 0; j < 7; j++)
            S[j] = fmaf(a, S[j], (mprev == mbase + 8 * j) ? a : 0.f);
        mprev = mn;
    };

    if (cnt == CSFIX) {
        #pragma unroll
        for (int q = 0; q < CSFIX; q++) body(q);
    } else {
        #pragma unroll 5
        for (int q = 0; q < cnt; q++) body(q);
    }

    #pragma unroll
    for (int j = 0; j < 7; j++) Brow[lane + 32 * j] = S[j];

    float t0    = __shfl_sync(0xffffffffu, tload, 0);
    float tlast = __shfl_sync(0xffffffffu, tload, cnt);
    if (lane < 4) Brow[NP + lane] = __expf(-gamma[lane] * (tlast - t0));
}

// ---------------------------------------------------------------------------
// Phase 2a: per-group scan (register-batched loads) + alphaG prep (folded in).
// ---------------------------------------------------------------------------
__global__ void __launch_bounds__(NP) k_phase2a(
        const float* __restrict__ alpha,
        const float* __restrict__ gamma)
{
    int g   = blockIdx.x;
    int tid = threadIdx.x;          // 224
    int k   = tid & 3;
    int c0  = g * GROUP;

    // alphaG prep in packed layout: one element per thread
    {
        int i = g * NP + tid;
        if (i < MM * AR2) {
            int mp = i / AR2;
            int p  = i % AR2;
            int l, u;
            if (p < 128) { l = p >> 2;        u = p & 3; }
            else         { l = (p - 128) >> 2; u = (p & 3) + 4; }
            int c = l + 32 * u;              // original column = lane + 32*j
            float v = 0.f;
            if (u < 7 && c < MM * KK) {
                int m = c >> 2, kk = c & 3;
                v = alpha[kk * (MM * MM) + mp * MM + m] * gamma[kk];
            }
            g_alphaG[i] = v;
        }
    }

    float carry = 0.f;
    float Aprod = 1.f;

    #pragma unroll 1
    for (int t = 0; t < GROUP; t += B2A) {
        float Av[B2A], Bv[B2A];
        #pragma unroll
        for (int i = 0; i < B2A; i++) {
            int ch = c0 + t + i;
            Av[i] = g_B[ch * BROW + NP + k];
            Bv[i] = g_B[ch * BROW + tid];
        }
        #pragma unroll
        for (int i = 0; i < B2A; i++) {
            int ch = c0 + t + i;
            g_carry[ch * NP + tid] = carry;
            if (tid < 4) g_Apre[ch * 4 + tid] = Aprod;
            carry = fmaf(Av[i], carry, Bv[i]);
            Aprod *= Av[i];
        }
    }
    g_GB[g * BROW + tid] = carry;
    if (tid < 4) g_GB[g * BROW + NP + tid] = Aprod;
}

// ---------------------------------------------------------------------------
// Phase 2b: scan the group transfers (single block, register-batched).
// ---------------------------------------------------------------------------
__global__ void __launch_bounds__(NP) k_phase2b()
{
    int tid = threadIdx.x;          // 224
    int k   = tid & 3;
    float carry = 0.f;

    #pragma unroll 1
    for (int t = 0; t < NGROUP; t += B2B) {
        float Av[B2B], Bv[B2B];
        #pragma unroll
        for (int i = 0; i < B2B; i++) {
            int g = t + i;
            Av[i] = g_GB[g * BROW + NP + k];
            Bv[i] = g_GB[g * BROW + tid];
        }
        #pragma unroll
        for (int i = 0; i < B2B; i++) {
            int g = t + i;
            g_gc[g * NP + tid] = carry;
            carry = fmaf(Av[i], carry, Bv[i]);
        }
    }
}

// ---------------------------------------------------------------------------
// Phase 3: replay with fixed-up carry; deferred reduction via smem transpose
// tile; fused final reduction (last block, deterministic fixed-order tree).
// ---------------------------------------------------------------------------
__global__ void __launch_bounds__(32 * W3, 2) k_phase3(
        const float* __restrict__ ti,
        const int*   __restrict__ mi32,
        const float* __restrict__ mu,
        const float* __restrict__ gamma,
        float* __restrict__ out,
        int N, int CS)
{
    extern __shared__ __align__(16) float dyn[];
    float* sA = dyn;                               // MM*AR2 floats
    for (int i = threadIdx.x; i < MM * AR2; i += blockDim.x)
        sA[i] = g_alphaG[i];
    __syncthreads();

    int wid  = threadIdx.x >> 5;
    int lane = threadIdx.x & 31;
    int w    = blockIdx.x * W3 + wid;

    long s = (long)w * CS;
    int  e = (int)min((long)N, s + CS);
    const bool active = (w < CNUM) && (s < N);
    const int cnt = active ? (e - (int)s) : 0;

    if (active) {
        float* sT = dyn + MM * AR2 + wid * (EMAX * TROW);

        const int shift = detect_shift(mi32, lane);

        // preload ti/mi: lane q holds index s-1+q (clamped)
        long li = s - 1 + lane;
        if (li < 0) li = 0;
        if (li > N - 1) li = N - 1;
        float tload = ti[li];
        int   mload = mi32[li << shift];

        const float4 g4 = *(const float4*)gamma;

        // batch exps into row pads: lane q -> sT[q*TROW+32..35]
        {
            float tnext = __shfl_down_sync(0xffffffffu, tload, 1);
            float dtq   = tnext - tload;
            if (lane < cnt) {
                float4 av;
                av.x = __expf(-g4.x * dtq);
                av.y = __expf(-g4.y * dtq);
                av.z = __expf(-g4.z * dtq);
                av.w = __expf(-g4.w * dtq);
                *(float4*)&sT[lane * TROW + 32] = av;
            }
        }
        __syncwarp();

        const int kidx  = lane & 3;
        const int mbase = lane >> 2;
        const int grp   = w / GROUP;

        // carry fixup: S = Apre * group_carry + local_prefix
        const float Apre = g_Apre[w * 4 + kidx];
        float S[7];
        #pragma unroll
        for (int j = 0; j < 7; j++)
            S[j] = fmaf(Apre, g_gc[grp * NP + lane + 32 * j],
                        g_carry[w * NP + lane + 32 * j]);

        int mprev = (s > 0) ? __shfl_sync(0xffffffffu, mload, 0) : -1;

        auto body = [&](int q) {
            int   mn = __shfl_sync(0xffffffffu, mload, q + 1);
            float a  = sT[q * TROW + 32 + kidx];
            #pragma unroll
            for (int j = 0; j < 7; j++)
                S[j] = fmaf(a, S[j], (mprev == mbase + 8 * j) ? a : 0.f);

            const float4* rb = (const float4*)(sA + mn * AR2);
            float4 va = rb[lane];
            float4 vb = rb[32 + lane];
            float dot = va.x * S[0];
            dot = fmaf(va.y, S[1], dot);
            dot = fmaf(va.z, S[2], dot);
            dot = fmaf(va.w, S[3], dot);
            dot = fmaf(vb.x, S[4], dot);
            dot = fmaf(vb.y, S[5], dot);
            dot = fmaf(vb.z, S[6], dot);

            sT[q * TROW + lane] = dot;
            mprev = mn;
        };

        if (cnt == CSFIX) {
            #pragma unroll
            for (int q = 0; q < CSFIX; q++) body(q);
        } else {
            #pragma unroll 5
            for (int q = 0; q < cnt; q++) body(q);
        }
        __syncwarp();

        // Pass B: lane q reduces event q's 32 partials (fixed order) + log
        float val = 0.f;
        if (lane < cnt) {
            const float4* r4 = (const float4*)&sT[lane * TROW];
            float4 v0 = r4[0], v1 = r4[1], v2 = r4[2], v3 = r4[3];
            float4 v4 = r4[4], v5 = r4[5], v6 = r4[6], v7 = r4[7];
            float s0 = ((v0.x + v0.y) + (v0.z + v0.w)) + ((v1.x + v1.y) + (v1.z + v1.w));
            float s1 = ((v2.x + v2.y) + (v2.z + v2.w)) + ((v3.x + v3.y) + (v3.z + v3.w));
            float s2 = ((v4.x + v4.y) + (v4.z + v4.w)) + ((v5.x + v5.y) + (v5.z + v5.w));
            float s3 = ((v6.x + v6.y) + (v6.z + v6.w)) + ((v7.x + v7.y) + (v7.z + v7.w));
            float sum = (s0 + s1) + (s2 + s3);
            val = __logf(mu[(int)s + lane] + sum);
        }

        #pragma unroll
        for (int o = 16; o > 0; o >>= 1)
            val += __shfl_xor_sync(0xffffffffu, val, o);

        if (lane == 0) g_partial[w] = (double)val;
    } else if (w < CNUM) {
        if (lane == 0) g_partial[w] = 0.0;
    }

    // ---- fused final reduction: last block sums g_partial deterministically
    __syncthreads();
    __shared__ int s_last;
    if (threadIdx.x == 0) {
        __threadfence();
        s_last = (atomicAdd(&g_done, 1) == (int)gridDim.x - 1);
    }
    __syncthreads();
    if (!s_last) return;

    __shared__ double sd[512];
    int tid = threadIdx.x;
    double v = 0.0;
    #pragma unroll
    for (int i = 0; i < CNUM / 512; i++)
        v += ((volatile double*)g_partial)[tid + i * 512];
    sd[tid] = v;
    __syncthreads();
    #pragma unroll
    for (int o = 256; o > 0; o >>= 1) {
        if (tid < o) sd[tid] += sd[tid + o];
        __syncthreads();
    }
    if (tid == 0) { out[0] = (float)sd[0]; g_done = 0; }
}

// ---------------------------------------------------------------------------
extern "C" void kernel_launch(void* const* d_in, const int* in_sizes, int n_in,
                              void* d_out, int out_size)
{
    const float* ti    = (const float*)d_in[0];
    const int*   mi32  = (const int*)  d_in[1];   // int32 or int64; runtime-detected
    const float* mu    = (const float*)d_in[2];
    const float* alpha = (const float*)d_in[3];
    const float* gamma = (const float*)d_in[4];
    float* out = (float*)d_out;

    int N  = in_sizes[0];
    int CS = (N + CNUM - 1) / CNUM;   // 25 for N=200000 (must be <= EMAX)

    const int P3_SMEM = (MM * AR2 + W3 * EMAX * TROW) * 4;   // 111104 B -> 2 blocks/SM
    cudaFuncSetAttribute(k_phase3, cudaFuncAttributeMaxDynamicSharedMemorySize, P3_SMEM);

    k_phase1 <<<CNUM / 8, 256>>>(ti, mi32, gamma, N, CS);
    k_phase2a<<<NGROUP, NP>>>(alpha, gamma);
    k_phase2b<<<1, NP>>>();
    k_phase3 <<<CNUM / W3, 32 * W3, P3_SMEM>>>(ti, mi32, mu, gamma, out, N, CS);
}